// round 15
// baseline (speedup 1.0000x reference)
#include <cuda_runtime.h>
#include <cuda_bf16.h>
#include <cuda_fp16.h>
#include <math.h>
#include <stdint.h>

#define N0 20000
#define N1 20000
#define N2 10000
#define NA 600000
#define NE 400000
#define HD 128
#define RR 13
#define LL 2
#define SLAB (N0 * HD)
#define CBASE 20000           // per-relation counter stride (edge CSR)
#define NCNT 260096           // 1016 * 256 (edge counter array, zero-padded)
#define NBLK 1016
#define NCNT2 20224           // 79 * 256 (atom counter array, zero-padded)
#define NBLK2 79
#define NROWS (N0 + N1 + N2)  // 50000
#define NG 6                  // relation groups per layer

// ---------------- scratch (static device globals; no allocation) ---------------
__device__ float g_x0[N0 * HD];
__device__ float g_x1[N1 * HD];
__device__ float g_x2[N2 * HD];
__device__ float g_a0[N0 * HD];
__device__ float g_a1[N1 * HD];
__device__ float g_a2[N2 * HD];
__device__ __half g_xlh[RR * SLAB];  // per-relation fp16 Wl outputs
__device__ float g_xr[RR * SLAB];    // per-relation fp32 Wr outputs
__device__ float g_cbias[LL * 3 * HD];
__device__ float g_zero128[HD];      // zero bias (zero-initialized)
// edge CSR scratch
__device__ int g_counts[NCNT];
__device__ int g_offs[NCNT];
__device__ int g_fill[NCNT];
__device__ int g_sums[NBLK];
__device__ int g_ssorted[RR * NE];   // src ids grouped by dst
// atom CSR scratch
__device__ int g_counts2[NCNT2];
__device__ int g_offs2[NCNT2];
__device__ int g_fill2[NCNT2];
__device__ int g_sums2[NBLK2];
__device__ int g_asorted[NA];        // atom ids grouped by chemical

__constant__ int c_RD[RR] = {2, 2, 1, 1, 1, 1, 1, 0, 0, 0, 0, 0, 2};

// ---------------- helpers ----------------
// sm_103a has no redux.f32 — SHFL butterfly is the floor (verified R13).
__device__ __forceinline__ float wsum(float v) {
#pragma unroll
    for (int o = 16; o; o >>= 1) v += __shfl_xor_sync(0xffffffffu, v, o);
    return v;
}
__device__ __forceinline__ void ldsm4(uint32_t* r, uint32_t addr) {
    asm volatile(
        "ldmatrix.sync.aligned.m8n8.x4.shared.b16 {%0,%1,%2,%3}, [%4];"
        : "=r"(r[0]), "=r"(r[1]), "=r"(r[2]), "=r"(r[3])
        : "r"(addr));
}
__device__ __forceinline__ void ldsm4t(uint32_t* r, uint32_t addr) {
    asm volatile(
        "ldmatrix.sync.aligned.m8n8.x4.trans.shared.b16 {%0,%1,%2,%3}, [%4];"
        : "=r"(r[0]), "=r"(r[1]), "=r"(r[2]), "=r"(r[3])
        : "r"(addr));
}
__device__ __forceinline__ void mma16816(float* d, const uint32_t* a,
                                         const uint32_t* b) {
    asm volatile(
        "mma.sync.aligned.m16n8k16.row.col.f32.bf16.bf16.f32 "
        "{%0,%1,%2,%3}, {%4,%5,%6,%7}, {%8,%9}, {%0,%1,%2,%3};"
        : "+f"(d[0]), "+f"(d[1]), "+f"(d[2]), "+f"(d[3])
        : "r"(a[0]), "r"(a[1]), "r"(a[2]), "r"(a[3]), "r"(b[0]), "r"(b[1]));
}
__device__ __forceinline__ void split4(float4 v, uint2& hi, uint2& lo) {
    __nv_bfloat162 h0 = __floats2bfloat162_rn(v.x, v.y);
    __nv_bfloat162 h1 = __floats2bfloat162_rn(v.z, v.w);
    float2 f0 = __bfloat1622float2(h0);
    float2 f1 = __bfloat1622float2(h1);
    __nv_bfloat162 l0 = __floats2bfloat162_rn(v.x - f0.x, v.y - f0.y);
    __nv_bfloat162 l1 = __floats2bfloat162_rn(v.z - f1.x, v.w - f1.y);
    hi = make_uint2(*(uint32_t*)&h0, *(uint32_t*)&h1);
    lo = make_uint2(*(uint32_t*)&l0, *(uint32_t*)&l1);
}

// ---------------- zero kernels ----------------
__global__ void zero_i_kernel(int* p, int n) {
    int i = blockIdx.x * blockDim.x + threadIdx.x;
    int st = gridDim.x * blockDim.x;
    for (; i < n; i += st) p[i] = 0;
}

// ---------------- generic CSR build pieces ----------------
__global__ void hist_kernel(const int* __restrict__ eir,
                            int* __restrict__ cnt) {
    int r = blockIdx.y;
    int i = blockIdx.x * blockDim.x + threadIdx.x;
    if (i < NE) atomicAdd(&cnt[r * CBASE + eir[(size_t)r * 2 * NE + NE + i]], 1);
}
__global__ void hist2_kernel(const int* __restrict__ hyper,
                             int* __restrict__ cnt) {
    int i = blockIdx.x * blockDim.x + threadIdx.x;
    if (i < NA) atomicAdd(&cnt[hyper[i]], 1);
}
__global__ void scanA_kernel(const int* __restrict__ cnt, int* __restrict__ out,
                             int* __restrict__ sums) {
    __shared__ int sh[256];
    int i = blockIdx.x * 256 + threadIdx.x;
    int v = cnt[i];
    sh[threadIdx.x] = v;
    __syncthreads();
    for (int o = 1; o < 256; o <<= 1) {
        int t = (threadIdx.x >= o) ? sh[threadIdx.x - o] : 0;
        __syncthreads();
        sh[threadIdx.x] += t;
        __syncthreads();
    }
    out[i] = sh[threadIdx.x] - v;
    if (threadIdx.x == 255) sums[blockIdx.x] = sh[255];
}
__global__ void scanB_kernel(int* __restrict__ sums, int n) {
    __shared__ int sh[1024];
    int v = (threadIdx.x < n) ? sums[threadIdx.x] : 0;
    sh[threadIdx.x] = v;
    __syncthreads();
    for (int o = 1; o < 1024; o <<= 1) {
        int t = (threadIdx.x >= o) ? sh[threadIdx.x - o] : 0;
        __syncthreads();
        sh[threadIdx.x] += t;
        __syncthreads();
    }
    if (threadIdx.x < n) sums[threadIdx.x] = sh[threadIdx.x] - v;
}
__global__ void scanC_kernel(int* __restrict__ out, const int* __restrict__ sums,
                             int* __restrict__ fill) {
    int i = blockIdx.x * 256 + threadIdx.x;
    int v = out[i] + sums[blockIdx.x];
    out[i] = v;
    fill[i] = v;
}
__global__ void csr_scatter_kernel(const int* __restrict__ eir,
                                   int* __restrict__ fill,
                                   int* __restrict__ ssorted) {
    int r = blockIdx.y;
    int i = blockIdx.x * blockDim.x + threadIdx.x;
    if (i >= NE) return;
    int d = eir[(size_t)r * 2 * NE + NE + i];
    int s = eir[(size_t)r * 2 * NE + i];
    int pos = atomicAdd(&fill[r * CBASE + d], 1);
    ssorted[pos] = s;
}
__global__ void acsr_scatter_kernel(const int* __restrict__ hyper,
                                    int* __restrict__ fill,
                                    int* __restrict__ asorted) {
    int i = blockIdx.x * blockDim.x + threadIdx.x;
    if (i >= NA) return;
    int pos = atomicAdd(&fill[hyper[i]], 1);
    asorted[pos] = i;
}

// ---------------- atom aggregation: warp per chemical, no atomics ------------
__global__ __launch_bounds__(256) void atom_sum_kernel(
    const int* __restrict__ asorted, const int* __restrict__ aoffs,
    const float* __restrict__ xa, float* __restrict__ g) {
    int d = (blockIdx.x * blockDim.x + threadIdx.x) >> 5;
    int lane = threadIdx.x & 31;
    if (d >= N0) return;
    int beg = aoffs[d], end = aoffs[d + 1];
    float4 acc = make_float4(0.f, 0.f, 0.f, 0.f);
    int j = beg;
    for (; j + 1 < end; j += 2) {
        int a0 = asorted[j], a1 = asorted[j + 1];
        float4 v0 = *(const float4*)&xa[(size_t)a0 * 128 + lane * 4];
        float4 v1 = *(const float4*)&xa[(size_t)a1 * 128 + lane * 4];
        acc.x += v0.x + v1.x; acc.y += v0.y + v1.y;
        acc.z += v0.z + v1.z; acc.w += v0.w + v1.w;
    }
    if (j < end) {
        int a0 = asorted[j];
        float4 v0 = *(const float4*)&xa[(size_t)a0 * 128 + lane * 4];
        acc.x += v0.x; acc.y += v0.y; acc.z += v0.z; acc.w += v0.w;
    }
    *(float4*)&g[(size_t)d * 128 + lane * 4] = acc;
}

// x0 = gemm_out/max(cnt,1) + x_chem
__global__ void combine_kernel(const float* __restrict__ t,
                               const int* __restrict__ cnt,
                               const float* __restrict__ xc,
                               float* __restrict__ out, int n) {
    int i = blockIdx.x * blockDim.x + threadIdx.x;
    if (i < n) out[i] = t[i] / fmaxf((float)cnt[i >> 7], 1.f) + xc[i];
}

// ---------------- tensor-core bf16x3 GEMM core (runtime halfout) -------------
__device__ __forceinline__ void tc_gemm_core(const float* __restrict__ A,
                                             const float* __restrict__ B,
                                             const float* __restrict__ bias,
                                             void* __restrict__ Cv, int M,
                                             int halfout) {
    extern __shared__ __nv_bfloat16 sm[];
    __nv_bfloat16* sAh = sm;
    __nv_bfloat16* sAl = sm + 8192;
    __nv_bfloat16* sBh = sm + 16384;
    __nv_bfloat16* sBl = sm + 24576;
    const int tid = threadIdx.x;
    const int lane = tid & 31, warp = tid >> 5;
    const int wm = warp & 3, wn = warp >> 2;
    const int rowBase = blockIdx.x * 128;
    if (rowBase >= M) return;

    float acc[2][8][4];
#pragma unroll
    for (int a = 0; a < 2; ++a)
#pragma unroll
        for (int b = 0; b < 8; ++b)
#pragma unroll
            for (int c = 0; c < 4; ++c) acc[a][b][c] = 0.f;

    uint32_t sAh_b = (uint32_t)__cvta_generic_to_shared(sAh);
    uint32_t sAl_b = (uint32_t)__cvta_generic_to_shared(sAl);
    uint32_t sBh_b = (uint32_t)__cvta_generic_to_shared(sBh);
    uint32_t sBl_b = (uint32_t)__cvta_generic_to_shared(sBl);

    for (int kc = 0; kc < 128; kc += 64) {
        __syncthreads();
#pragma unroll
        for (int i = 0; i < 8; ++i) {
            int j = tid + 256 * i;
            int row = j >> 4, c4 = j & 15;
            float4 v = make_float4(0.f, 0.f, 0.f, 0.f);
            if (rowBase + row < M)
                v = *(const float4*)&A[(size_t)(rowBase + row) * 128 + kc +
                                       c4 * 4];
            uint2 h, l;
            split4(v, h, l);
            int off = row * 64 + (((c4 >> 1) ^ (row & 7)) << 3) + (c4 & 1) * 4;
            *(uint2*)&sAh[off] = h;
            *(uint2*)&sAl[off] = l;
        }
#pragma unroll
        for (int i = 0; i < 8; ++i) {
            int j = tid + 256 * i;
            int row = j >> 5, c4 = j & 31;
            float4 v = *(const float4*)&B[(size_t)(kc + row) * 128 + c4 * 4];
            uint2 h, l;
            split4(v, h, l);
            int off = row * 128 + (((c4 >> 1) ^ (row & 7)) << 3) + (c4 & 1) * 4;
            *(uint2*)&sBh[off] = h;
            *(uint2*)&sBl[off] = l;
        }
        __syncthreads();
#pragma unroll
        for (int s = 0; s < 4; ++s) {
            uint32_t ah[2][4], al[2][4];
#pragma unroll
            for (int mf = 0; mf < 2; ++mf) {
                int mr = wm * 32 + mf * 16 + (lane & 15);
                int ck = 2 * s + (lane >> 4);
                uint32_t off = (uint32_t)(mr * 64 + ((ck ^ (mr & 7)) << 3)) * 2;
                ldsm4(ah[mf], sAh_b + off);
                ldsm4(al[mf], sAl_b + off);
            }
#pragma unroll
            for (int nf2 = 0; nf2 < 4; ++nf2) {
                int kr = s * 16 + (lane & 7) + ((lane >> 3) & 1) * 8;
                int cn = wn * 8 + nf2 * 2 + (lane >> 4);
                uint32_t off =
                    (uint32_t)(kr * 128 + ((cn ^ (kr & 7)) << 3)) * 2;
                uint32_t bh[4], bl[4];
                ldsm4t(bh, sBh_b + off);
                ldsm4t(bl, sBl_b + off);
#pragma unroll
                for (int mf = 0; mf < 2; ++mf) {
                    mma16816(acc[mf][nf2 * 2], ah[mf], bh);
                    mma16816(acc[mf][nf2 * 2], ah[mf], bl);
                    mma16816(acc[mf][nf2 * 2], al[mf], bh);
                    mma16816(acc[mf][nf2 * 2 + 1], ah[mf], bh + 2);
                    mma16816(acc[mf][nf2 * 2 + 1], ah[mf], bl + 2);
                    mma16816(acc[mf][nf2 * 2 + 1], al[mf], bh + 2);
                }
            }
        }
    }
    int c0 = wn * 64 + (lane & 3) * 2;
#pragma unroll
    for (int mf = 0; mf < 2; ++mf) {
        int r0 = rowBase + wm * 32 + mf * 16 + (lane >> 2);
#pragma unroll
        for (int nf = 0; nf < 8; ++nf) {
            int col = c0 + nf * 8;
            float2 bv = *(const float2*)&bias[col];
            if (halfout) {
                __half* C = (__half*)Cv;
                if (r0 < M)
                    *(__half2*)&C[(size_t)r0 * 128 + col] = __floats2half2_rn(
                        acc[mf][nf][0] + bv.x, acc[mf][nf][1] + bv.y);
                if (r0 + 8 < M)
                    *(__half2*)&C[(size_t)(r0 + 8) * 128 + col] =
                        __floats2half2_rn(acc[mf][nf][2] + bv.x,
                                          acc[mf][nf][3] + bv.y);
            } else {
                float* C = (float*)Cv;
                if (r0 < M) {
                    C[(size_t)r0 * 128 + col] = acc[mf][nf][0] + bv.x;
                    C[(size_t)r0 * 128 + col + 1] = acc[mf][nf][1] + bv.y;
                }
                if (r0 + 8 < M) {
                    C[(size_t)(r0 + 8) * 128 + col] = acc[mf][nf][2] + bv.x;
                    C[(size_t)(r0 + 8) * 128 + col + 1] = acc[mf][nf][3] + bv.y;
                }
            }
        }
    }
}

// batched GEMM: up to 6 independent 128-N GEMMs in one launch (grid.y)
struct GBatch {
    const float* A[6];
    const float* W[6];
    const float* bias[6];
    void* C[6];
    int M[6];
    int halfout[6];
};
__global__ __launch_bounds__(256, 2) void tc_gemm_batch_kernel(GBatch gb) {
    int z = blockIdx.y;
    tc_gemm_core(gb.A[z], gb.W[z], gb.bias[z], gb.C[z], gb.M[z],
                 gb.halfout[z]);
}
__global__ __launch_bounds__(256, 2) void tc_gemm_f32_kernel(
    const float* __restrict__ A, const float* __restrict__ B,
    const float* __restrict__ bias, float* __restrict__ C, int M) {
    tc_gemm_core(A, B, bias, C, M, 0);
}

// ---------------- merged CSR edge aggregation (grid.y = relation in group) ---
struct EGroup {
    const __half* xl[3];
    const float* xr[3];
    const float* att[3];
    float* agg[3];
    int Nd[3];
    int robase[3];
    int store[3];
};
__global__ __launch_bounds__(256) void edge_group_kernel(
    EGroup eg, const int* __restrict__ ssorted, const int* __restrict__ offs) {
    int z = blockIdx.y;
    int d = (blockIdx.x * blockDim.x + threadIdx.x) >> 5;
    int lane = threadIdx.x & 31;
    if (d >= eg.Nd[z]) return;
    const __half* xl = eg.xl[z];
    const float* xr = eg.xr[z];
    int beg = offs[eg.robase[z] + d], end = offs[eg.robase[z] + d + 1];
    float* o = &eg.agg[z][(size_t)d * 128 + lane * 4];
    bool store = eg.store[z] != 0;
    if (beg == end) {
        if (store) *(float4*)o = make_float4(0.f, 0.f, 0.f, 0.f);
        return;
    }
    float4 r4 = *(const float4*)&xr[(size_t)d * 128 + lane * 4];
    float4 av = *(const float4*)&eg.att[z][lane * 4];
    float4 acc = make_float4(0.f, 0.f, 0.f, 0.f);
    float sden = 0.f;
    int j = beg;
    for (; j + 3 < end; j += 4) {
        int s0 = ssorted[j], s1 = ssorted[j + 1];
        int s2 = ssorted[j + 2], s3 = ssorted[j + 3];
        uint2 u0 = *(const uint2*)&xl[(size_t)s0 * 128 + lane * 4];
        uint2 u1 = *(const uint2*)&xl[(size_t)s1 * 128 + lane * 4];
        uint2 u2 = *(const uint2*)&xl[(size_t)s2 * 128 + lane * 4];
        uint2 u3 = *(const uint2*)&xl[(size_t)s3 * 128 + lane * 4];
        float2 A01 = __half22float2(*(__half2*)&u0.x);
        float2 A23 = __half22float2(*(__half2*)&u0.y);
        float2 B01 = __half22float2(*(__half2*)&u1.x);
        float2 B23 = __half22float2(*(__half2*)&u1.y);
        float2 C01 = __half22float2(*(__half2*)&u2.x);
        float2 C23 = __half22float2(*(__half2*)&u2.y);
        float2 D01 = __half22float2(*(__half2*)&u3.x);
        float2 D23 = __half22float2(*(__half2*)&u3.y);
        float t, pA, pB, pC, pD;
        t = A01.x + r4.x; t = t > 0.f ? t : 0.2f * t; pA = t * av.x;
        t = A01.y + r4.y; t = t > 0.f ? t : 0.2f * t; pA += t * av.y;
        t = A23.x + r4.z; t = t > 0.f ? t : 0.2f * t; pA += t * av.z;
        t = A23.y + r4.w; t = t > 0.f ? t : 0.2f * t; pA += t * av.w;
        t = B01.x + r4.x; t = t > 0.f ? t : 0.2f * t; pB = t * av.x;
        t = B01.y + r4.y; t = t > 0.f ? t : 0.2f * t; pB += t * av.y;
        t = B23.x + r4.z; t = t > 0.f ? t : 0.2f * t; pB += t * av.z;
        t = B23.y + r4.w; t = t > 0.f ? t : 0.2f * t; pB += t * av.w;
        t = C01.x + r4.x; t = t > 0.f ? t : 0.2f * t; pC = t * av.x;
        t = C01.y + r4.y; t = t > 0.f ? t : 0.2f * t; pC += t * av.y;
        t = C23.x + r4.z; t = t > 0.f ? t : 0.2f * t; pC += t * av.z;
        t = C23.y + r4.w; t = t > 0.f ? t : 0.2f * t; pC += t * av.w;
        t = D01.x + r4.x; t = t > 0.f ? t : 0.2f * t; pD = t * av.x;
        t = D01.y + r4.y; t = t > 0.f ? t : 0.2f * t; pD += t * av.y;
        t = D23.x + r4.z; t = t > 0.f ? t : 0.2f * t; pD += t * av.z;
        t = D23.y + r4.w; t = t > 0.f ? t : 0.2f * t; pD += t * av.w;
        pA = wsum(pA); pB = wsum(pB); pC = wsum(pC); pD = wsum(pD);
        float eA = __expf(pA), eB = __expf(pB);
        float eC = __expf(pC), eD = __expf(pD);
        acc.x += eA * A01.x + eB * B01.x + eC * C01.x + eD * D01.x;
        acc.y += eA * A01.y + eB * B01.y + eC * C01.y + eD * D01.y;
        acc.z += eA * A23.x + eB * B23.x + eC * C23.x + eD * D23.x;
        acc.w += eA * A23.y + eB * B23.y + eC * C23.y + eD * D23.y;
        sden += (eA + eB) + (eC + eD);
    }
    for (; j < end; ++j) {
        int s0 = ssorted[j];
        uint2 u0 = *(const uint2*)&xl[(size_t)s0 * 128 + lane * 4];
        float2 A01 = __half22float2(*(__half2*)&u0.x);
        float2 A23 = __half22float2(*(__half2*)&u0.y);
        float t, pA;
        t = A01.x + r4.x; t = t > 0.f ? t : 0.2f * t; pA = t * av.x;
        t = A01.y + r4.y; t = t > 0.f ? t : 0.2f * t; pA += t * av.y;
        t = A23.x + r4.z; t = t > 0.f ? t : 0.2f * t; pA += t * av.z;
        t = A23.y + r4.w; t = t > 0.f ? t : 0.2f * t; pA += t * av.w;
        pA = wsum(pA);
        float eA = __expf(pA);
        acc.x += eA * A01.x; acc.y += eA * A01.y;
        acc.z += eA * A23.x; acc.w += eA * A23.y;
        sden += eA;
    }
    float inv = 1.f / fmaxf(sden, 1e-16f);
    if (store) {
        *(float4*)o = make_float4(acc.x * inv, acc.y * inv, acc.z * inv,
                                  acc.w * inv);
    } else {
        float4 g = *(float4*)o;
        g.x += acc.x * inv; g.y += acc.y * inv;
        g.z += acc.z * inv; g.w += acc.w * inv;
        *(float4*)o = g;
    }
}

// combined GATv2 output bias per (layer, dst type)
__global__ void cbias2_kernel(const float* __restrict__ cb,
                              float* __restrict__ out) {
    int l = blockIdx.x;
    int c = threadIdx.x;
    float s[3] = {0.f, 0.f, 0.f};
#pragma unroll
    for (int r = 0; r < RR; ++r) s[c_RD[r]] += cb[(l * RR + r) * HD + c];
    out[(l * 3 + 0) * HD + c] = s[0];
    out[(l * 3 + 1) * HD + c] = s[1];
    out[(l * 3 + 2) * HD + c] = s[2];
}

// ---------------- merged layernorm + relu over all 3 types -------------------
__global__ void ln_relu_all_kernel(const float* __restrict__ a0,
                                   const float* __restrict__ a1,
                                   const float* __restrict__ a2,
                                   float* __restrict__ x0,
                                   float* __restrict__ x1,
                                   float* __restrict__ x2,
                                   const float* __restrict__ cb3,
                                   const float* __restrict__ g3,
                                   const float* __restrict__ b3) {
    int row = (blockIdx.x * blockDim.x + threadIdx.x) >> 5;
    int lane = threadIdx.x & 31;
    if (row >= NROWS) return;
    int t, lr;
    const float* in;
    float* out;
    if (row < N0) { t = 0; lr = row; in = a0; out = x0; }
    else if (row < N0 + N1) { t = 1; lr = row - N0; in = a1; out = x1; }
    else { t = 2; lr = row - N0 - N1; in = a2; out = x2; }
    float4 v = *(const float4*)&in[(size_t)lr * 128 + lane * 4];
    float4 cv = *(const float4*)&cb3[t * HD + lane * 4];
    v.x += cv.x; v.y += cv.y; v.z += cv.z; v.w += cv.w;
    float s = v.x + v.y + v.z + v.w;
    s = wsum(s);
    float mu = s * (1.f / 128.f);
    float d0 = v.x - mu, d1 = v.y - mu, d2 = v.z - mu, d3 = v.w - mu;
    float ss = d0 * d0 + d1 * d1 + d2 * d2 + d3 * d3;
    ss = wsum(ss);
    float inv = rsqrtf(ss * (1.f / 128.f) + 1e-5f);
    float4 gv = *(const float4*)&g3[t * HD + lane * 4];
    float4 bv = *(const float4*)&b3[t * HD + lane * 4];
    float4 o;
    o.x = fmaxf(d0 * inv * gv.x + bv.x, 0.f);
    o.y = fmaxf(d1 * inv * gv.y + bv.y, 0.f);
    o.z = fmaxf(d2 * inv * gv.z + bv.z, 0.f);
    o.w = fmaxf(d3 * inv * gv.w + bv.w, 0.f);
    *(float4*)&out[(size_t)lr * 128 + lane * 4] = o;
}

// ---------------- prediction head ----------------
__global__ void pred_kernel(const float* __restrict__ x,
                            const float* __restrict__ Wp,
                            const float* __restrict__ bp,
                            float* __restrict__ out, int N) {
    int row = (blockIdx.x * blockDim.x + threadIdx.x) >> 5;
    int lane = threadIdx.x & 31;
    if (row >= N) return;
    float4 xv = *(const float4*)&x[(size_t)row * 128 + lane * 4];
    float4 w01 = *(const float4*)&Wp[lane * 8];
    float4 w23 = *(const float4*)&Wp[lane * 8 + 4];
    float a0 = xv.x * w01.x + xv.y * w01.z + xv.z * w23.x + xv.w * w23.z;
    float a1 = xv.x * w01.y + xv.y * w01.w + xv.z * w23.y + xv.w * w23.w;
    a0 = wsum(a0);
    a1 = wsum(a1);
    if (lane == 0) {
        out[row * 2 + 0] = a0 + bp[0];
        out[row * 2 + 1] = a1 + bp[1];
    }
}

// ---------------- host orchestration ----------------
extern "C" void kernel_launch(void* const* d_in, const int* in_sizes, int n_in,
                              void* d_out, int out_size) {
    const float* x_atom = (const float*)d_in[0];
    const float* x_chem = (const float*)d_in[1];
    const float* x_gene = (const float*)d_in[2];
    const float* x_assay = (const float*)d_in[3];
    const float* W_mol = (const float*)d_in[4];
    const float* Wl = (const float*)d_in[5];
    const float* Wr = (const float*)d_in[6];
    const float* bl = (const float*)d_in[7];
    const float* br = (const float*)d_in[8];
    const float* att = (const float*)d_in[9];
    const float* cb = (const float*)d_in[10];
    const float* lng = (const float*)d_in[11];
    const float* lnb = (const float*)d_in[12];
    const float* Wp = (const float*)d_in[13];
    const float* bp = (const float*)d_in[14];
    const int* hyper = (const int*)d_in[15];
    const int* eir = (const int*)d_in[16];
    float* out = (float*)d_out;
    (void)in_sizes; (void)n_in; (void)out_size;

    float *px0, *px1, *px2, *pa0, *pa1, *pa2, *pxr, *pcb, *pz;
    __half* pxlh;
    int *pcounts, *poffs, *pfill, *psums, *pss;
    int *pcounts2, *poffs2, *pfill2, *psums2, *pas;
    cudaGetSymbolAddress((void**)&px0, g_x0);
    cudaGetSymbolAddress((void**)&px1, g_x1);
    cudaGetSymbolAddress((void**)&px2, g_x2);
    cudaGetSymbolAddress((void**)&pa0, g_a0);
    cudaGetSymbolAddress((void**)&pa1, g_a1);
    cudaGetSymbolAddress((void**)&pa2, g_a2);
    cudaGetSymbolAddress((void**)&pxlh, g_xlh);
    cudaGetSymbolAddress((void**)&pxr, g_xr);
    cudaGetSymbolAddress((void**)&pcb, g_cbias);
    cudaGetSymbolAddress((void**)&pz, g_zero128);
    cudaGetSymbolAddress((void**)&pcounts, g_counts);
    cudaGetSymbolAddress((void**)&poffs, g_offs);
    cudaGetSymbolAddress((void**)&pfill, g_fill);
    cudaGetSymbolAddress((void**)&psums, g_sums);
    cudaGetSymbolAddress((void**)&pss, g_ssorted);
    cudaGetSymbolAddress((void**)&pcounts2, g_counts2);
    cudaGetSymbolAddress((void**)&poffs2, g_offs2);
    cudaGetSymbolAddress((void**)&pfill2, g_fill2);
    cudaGetSymbolAddress((void**)&psums2, g_sums2);
    cudaGetSymbolAddress((void**)&pas, g_asorted);

    // 2-stream topology (teardown-safe configuration)
    static cudaStream_t s1 = nullptr;
    static cudaEvent_t evStart, evFork, evCSR, evG[LL * NG], evL[LL];
    if (!s1) {
        cudaStreamCreateWithFlags(&s1, cudaStreamNonBlocking);
        cudaEventCreateWithFlags(&evStart, cudaEventDisableTiming);
        cudaEventCreateWithFlags(&evFork, cudaEventDisableTiming);
        cudaEventCreateWithFlags(&evCSR, cudaEventDisableTiming);
        for (int i = 0; i < LL * NG; ++i)
            cudaEventCreateWithFlags(&evG[i], cudaEventDisableTiming);
        for (int i = 0; i < LL; ++i)
            cudaEventCreateWithFlags(&evL[i], cudaEventDisableTiming);
    }

    const int T = 256;
    const int SMEMB = 65536;

    cudaFuncSetAttribute(tc_gemm_batch_kernel,
                         cudaFuncAttributeMaxDynamicSharedMemorySize, SMEMB);
    cudaFuncSetAttribute(tc_gemm_f32_kernel,
                         cudaFuncAttributeMaxDynamicSharedMemorySize, SMEMB);

    static const int RS[RR] = {0, 0, 0, 0, 0, 2, 1, 2, 2, 1, 1, 1, 1};
    static const int RD[RR] = {2, 2, 1, 1, 1, 1, 1, 0, 0, 0, 0, 0, 2};
    // groups: distinct dst types per group; G0 = input-only relations (5,12)
    static const int GREL[NG][3] = {{5, 12, -1}, {6, 0, 7}, {2, 1, 8},
                                    {3, 9, -1},  {4, 10, -1}, {11, -1, -1}};
    static const int GNr[NG] = {2, 3, 3, 2, 2, 1};
    // STORE for the first relation of each dst type in group order
    static const bool FIRST[RR] = {false, false, false, false, false,
                                   true,  false, true,  false, false,
                                   false, false, true};
    const int NT[3] = {N0, N1, N2};

    auto launch_gemm_group = [&](int l, int g, const float* const xsrc[3],
                                 cudaStream_t st) {
        size_t lo = (size_t)l * RR;
        int n = GNr[g];
        GBatch gb;
        int mx = 0;
        for (int i = 0; i < n; ++i) {
            int r = GREL[g][i];
            size_t wo = lo + r;
            int s = RS[r], d = RD[r];
            gb.A[2 * i] = xsrc[s];
            gb.W[2 * i] = Wl + wo * HD * HD;
            gb.bias[2 * i] = bl + wo * HD;
            gb.C[2 * i] = pxlh + (size_t)r * SLAB;
            gb.M[2 * i] = NT[s];
            gb.halfout[2 * i] = 1;
            gb.A[2 * i + 1] = xsrc[d];
            gb.W[2 * i + 1] = Wr + wo * HD * HD;
            gb.bias[2 * i + 1] = br + wo * HD;
            gb.C[2 * i + 1] = pxr + (size_t)r * SLAB;
            gb.M[2 * i + 1] = NT[d];
            gb.halfout[2 * i + 1] = 0;
            if (NT[s] > mx) mx = NT[s];
            if (NT[d] > mx) mx = NT[d];
        }
        dim3 ggrid((mx + 127) / 128, 2 * n);
        tc_gemm_batch_kernel<<<ggrid, T, SMEMB, st>>>(gb);
        cudaEventRecord(evG[l * NG + g], st);
    };

    const float* xin[3] = {nullptr, x_gene, x_assay};  // G0 needs only inputs

    // s1: layer-0 G0 GEMMs (input-only) FIRST, then edge CSR + cbias
    cudaEventRecord(evStart, 0);
    cudaStreamWaitEvent(s1, evStart, 0);
    launch_gemm_group(0, 0, xin, s1);
    zero_i_kernel<<<256, T, 0, s1>>>(pcounts, NCNT);
    {
        dim3 hg((NE + T - 1) / T, RR);
        hist_kernel<<<hg, T, 0, s1>>>(eir, pcounts);
        scanA_kernel<<<NBLK, 256, 0, s1>>>(pcounts, poffs, psums);
        scanB_kernel<<<1, 1024, 0, s1>>>(psums, NBLK);
        scanC_kernel<<<NBLK, 256, 0, s1>>>(poffs, psums, pfill);
        csr_scatter_kernel<<<hg, T, 0, s1>>>(eir, pfill, pss);
        cbias2_kernel<<<LL, HD, 0, s1>>>(cb, pcb);
    }
    cudaEventRecord(evCSR, s1);

    // ---- stream 0 prelude: atom CSR -> gather-sum -> 20k GEMM -> combine ----
    zero_i_kernel<<<80, T>>>(pcounts2, NCNT2);
    hist2_kernel<<<(NA + T - 1) / T, T>>>(hyper, pcounts2);
    scanA_kernel<<<NBLK2, 256>>>(pcounts2, poffs2, psums2);
    scanB_kernel<<<1, 1024>>>(psums2, NBLK2);
    scanC_kernel<<<NBLK2, 256>>>(poffs2, psums2, pfill2);
    acsr_scatter_kernel<<<(NA + T - 1) / T, T>>>(hyper, pfill2, pas);
    atom_sum_kernel<<<(N0 * 32 + T - 1) / T, T>>>(pas, poffs2, x_atom, pa1);
    tc_gemm_f32_kernel<<<(N0 + 127) / 128, T, SMEMB>>>(pa1, W_mol, pz, pa0,
                                                       N0);
    combine_kernel<<<(N0 * HD + T - 1) / T, T>>>(pa0, pcounts2, x_chem, px0,
                                                 N0 * HD);
    cudaEventRecord(evFork, 0);
    cudaStreamWaitEvent(s1, evFork, 0);  // remaining GEMMs read px0
    cudaStreamWaitEvent(0, evCSR, 0);    // edge kernels need CSR + cbias

    const float* xsrc[3] = {px0, x_gene, x_assay};
    float* agg[3] = {pa0, pa1, pa2};

    for (int l = 0; l < LL; ++l) {
        size_t lo = (size_t)l * RR;

        for (int g = 0; g < NG; ++g) {
            if (!(l == 0 && g == 0)) launch_gemm_group(l, g, xsrc, s1);

            cudaStreamWaitEvent(0, evG[l * NG + g], 0);
            int n = GNr[g];
            EGroup egp;
            int mxd = 0;
            for (int i = 0; i < n; ++i) {
                int r = GREL[g][i];
                int d = RD[r];
                egp.xl[i] = pxlh + (size_t)r * SLAB;
                egp.xr[i] = pxr + (size_t)r * SLAB;
                egp.att[i] = att + (lo + r) * HD;
                egp.agg[i] = agg[d];
                egp.Nd[i] = NT[d];
                egp.robase[i] = r * CBASE;
                egp.store[i] = FIRST[r] ? 1 : 0;
                if (NT[d] > mxd) mxd = NT[d];
            }
            dim3 egrid((mxd * 32 + T - 1) / T, n);
            edge_group_kernel<<<egrid, T>>>(egp, pss, poffs);
        }
        ln_relu_all_kernel<<<(NROWS * 32 + T - 1) / T, T>>>(
            pa0, pa1, pa2, px0, px1, px2, pcb + l * 3 * HD,
            lng + (size_t)l * 3 * HD, lnb + (size_t)l * 3 * HD);
        xsrc[0] = px0; xsrc[1] = px1; xsrc[2] = px2;
        cudaEventRecord(evL[l], 0);
        cudaStreamWaitEvent(s1, evL[l], 0);
    }

    pred_kernel<<<(N0 * 32 + T - 1) / T, T>>>(px0, Wp, bp, out, N0);
}